// round 3
// baseline (speedup 1.0000x reference)
#include <cuda_runtime.h>

#define B_ 8
#define C_ 32
#define N_ 4096
#define NT 128
#define SPLIT 4
#define LUTN 2048
#define LUTSCALE 256.0f

// mean_c x[b,c,n] per (b,n)
__device__ float g_c[B_ * N_];
// split-K partial sums: [split][b][c][n]
__device__ float g_part[SPLIT][B_ * C_ * N_];

__global__ void mean_kernel(const float* __restrict__ x) {
    int idx = blockIdx.x * blockDim.x + threadIdx.x;
    if (idx >= B_ * N_) return;
    int b = idx >> 12;
    int n = idx & (N_ - 1);
    const float* p = x + ((size_t)b * C_) * N_ + n;
    float s = 0.f;
#pragma unroll
    for (int c = 0; c < C_; c++) s += p[(size_t)c * N_];
    g_c[idx] = s * (1.0f / C_);
}

// Partial: g_part[z][b,c,m] = sum_{n in slice} fea[b,c,n] * adj[n,m] * w(|cn-cm|)
// w(t) = 2/(1+e^t), evaluated via piecewise-linear smem LUT (no MUFU in loop)
__global__ __launch_bounds__(128, 5)
void gcn_partial_kernel(const float* __restrict__ x,
                        const float* __restrict__ adj) {
    __shared__ float s_fea[NT][36];     // [n][c], 144B rows: STS.128-friendly
    __shared__ float2 s_lut[LUTN];      // (slope, intercept) per segment
    __shared__ float s_c[NT];

    const int tid = threadIdx.x;
    const int b = blockIdx.y;
    const int z = blockIdx.z;
    const int m = blockIdx.x * 128 + tid;

    // build LUT: w(t) = 2/(1+exp(t)), linear per segment of width 1/LUTSCALE
#pragma unroll
    for (int j = tid; j < LUTN; j += 128) {
        float t0 = (float)j * (1.0f / LUTSCALE);
        float t1 = (float)(j + 1) * (1.0f / LUTSCALE);
        float w0 = 2.0f / (1.0f + expf(t0));
        float w1 = 2.0f / (1.0f + expf(t1));
        float a = (w1 - w0) * LUTSCALE;
        s_lut[j] = make_float2(a, w0 - a * t0);
    }

    const float cm = g_c[b * N_ + m];

    unsigned long long acc[16];
#pragma unroll
    for (int p = 0; p < 16; p++) acc[p] = 0ull;

    const float* xb = x + (size_t)b * C_ * N_;
    const int nbeg = z * (N_ / SPLIT);
    const int nend = nbeg + (N_ / SPLIT);

    for (int n0 = nbeg; n0 < nend; n0 += NT) {
        __syncthreads();
        // stage fea tile: s_fea[i][c] = x[b,c,n0+i], STS.128 over 4 channels
        {
            int i = tid;
#pragma unroll
            for (int k = 0; k < C_ / 4; k++) {
                float4 v;
                v.x = xb[(size_t)(4 * k + 0) * N_ + n0 + i];
                v.y = xb[(size_t)(4 * k + 1) * N_ + n0 + i];
                v.z = xb[(size_t)(4 * k + 2) * N_ + n0 + i];
                v.w = xb[(size_t)(4 * k + 3) * N_ + n0 + i];
                *reinterpret_cast<float4*>(&s_fea[i][4 * k]) = v;
            }
            s_c[i] = g_c[b * N_ + n0 + i];
        }
        __syncthreads();

        const float* adj_p = adj + (size_t)n0 * N_ + m;
#pragma unroll 4
        for (int n = 0; n < NT; n++) {
            float cn = s_c[n];
            float adjv = __ldg(adj_p + (size_t)n * N_);
            float t = fabsf(cn - cm);
            int i = __float2int_rd(t * LUTSCALE);
            i = min(i, LUTN - 1);
            float2 ab = s_lut[i];
            float w = fmaf(ab.x, t, ab.y) * adjv;
            unsigned long long w2;
            asm("mov.b64 %0, {%1, %1};" : "=l"(w2) : "f"(w));
            unsigned row_addr =
                (unsigned)__cvta_generic_to_shared(&s_fea[n][0]);
#pragma unroll
            for (int p = 0; p < 8; p++) {
                unsigned long long d0, d1;
                asm("ld.shared.v2.u64 {%0, %1}, [%2];"
                    : "=l"(d0), "=l"(d1) : "r"(row_addr + 16 * p));
                asm("fma.rn.f32x2 %0, %1, %2, %0;"
                    : "+l"(acc[2 * p]) : "l"(d0), "l"(w2));
                asm("fma.rn.f32x2 %0, %1, %2, %0;"
                    : "+l"(acc[2 * p + 1]) : "l"(d1), "l"(w2));
            }
        }
    }

    // write partials
    float* dst = &g_part[z][((size_t)b * C_) * N_ + m];
#pragma unroll
    for (int p = 0; p < 16; p++) {
        float lo, hi;
        asm("mov.b64 {%0, %1}, %2;" : "=f"(lo), "=f"(hi) : "l"(acc[p]));
        dst[(size_t)(2 * p) * N_] = lo;
        dst[(size_t)(2 * p + 1) * N_] = hi;
    }
}

// out = relu(para * sum_z part[z]), vectorized float4
__global__ void combine_kernel(const float* __restrict__ para,
                               float* __restrict__ out) {
    int idx = blockIdx.x * blockDim.x + threadIdx.x;  // over B*C*N/4
    const float4* pp = reinterpret_cast<const float4*>(para);
    float4 s = reinterpret_cast<const float4*>(g_part[0])[idx];
#pragma unroll
    for (int z = 1; z < SPLIT; z++) {
        float4 v = reinterpret_cast<const float4*>(g_part[z])[idx];
        s.x += v.x; s.y += v.y; s.z += v.z; s.w += v.w;
    }
    float4 pv = pp[idx & (C_ * N_ / 4 - 1)];
    float4 o;
    o.x = fmaxf(s.x * pv.x, 0.f);
    o.y = fmaxf(s.y * pv.y, 0.f);
    o.z = fmaxf(s.z * pv.z, 0.f);
    o.w = fmaxf(s.w * pv.w, 0.f);
    reinterpret_cast<float4*>(out)[idx] = o;
}

extern "C" void kernel_launch(void* const* d_in, const int* in_sizes, int n_in,
                              void* d_out, int out_size) {
    const float* x    = (const float*)d_in[0];  // [8,32,64,64]
    const float* para = (const float*)d_in[1];  // [1,32,64,64]
    const float* adj  = (const float*)d_in[2];  // [4096,4096]
    float* out = (float*)d_out;                 // [8,32,64,64]

    mean_kernel<<<(B_ * N_ + 255) / 256, 256>>>(x);

    dim3 grid(N_ / 128, B_, SPLIT);
    gcn_partial_kernel<<<grid, 128>>>(x, adj);

    combine_kernel<<<(B_ * C_ * N_ / 4) / 256, 256>>>(para, out);
}

// round 4
// speedup vs baseline: 1.4882x; 1.4882x over previous
#include <cuda_runtime.h>

#define B_ 8
#define C_ 32
#define N_ 4096
#define NT 128
#define SPLIT 8

// mean_c x[b,c,n] per (b,n)
__device__ float g_c[B_ * N_];
// split-K partial sums: [split][b][c][n]
__device__ float g_part[SPLIT][B_ * C_ * N_];

__global__ void mean_kernel(const float* __restrict__ x) {
    int idx = blockIdx.x * blockDim.x + threadIdx.x;
    if (idx >= B_ * N_) return;
    int b = idx >> 12;
    int n = idx & (N_ - 1);
    const float* p = x + ((size_t)b * C_) * N_ + n;
    float s = 0.f;
#pragma unroll
    for (int c = 0; c < C_; c++) s += p[(size_t)c * N_];
    g_c[idx] = s * (1.0f / C_);
}

// Each thread accumulates 2 output columns: m = bx*256+tid and m+128.
// g_part[z][b,c,m] = sum_{n in slice} fea[b,c,n] * adj[n,m] * w(n,m)
// w(n,m) = 2*min(e_n,e_m)/(e_n+e_m) with e = exp(c_adj); equals reference weight.
__global__ __launch_bounds__(128, 4)
void gcn_partial_kernel(const float* __restrict__ x,
                        const float* __restrict__ adj) {
    __shared__ float s_fea[NT][36];   // [n][c], 144B rows
    __shared__ float s_c[NT];

    const int tid = threadIdx.x;
    const int b = blockIdx.y;
    const int z = blockIdx.z;
    const int m0 = blockIdx.x * 256 + tid;      // first column
    const int m1 = m0 + 128;                    // second column

    const float em0 = __expf(g_c[b * N_ + m0]);
    const float em1 = __expf(g_c[b * N_ + m1]);

    unsigned long long accA[16], accB[16];
#pragma unroll
    for (int p = 0; p < 16; p++) { accA[p] = 0ull; accB[p] = 0ull; }

    const float* xb = x + (size_t)b * C_ * N_;
    const int nbeg = z * (N_ / SPLIT);
    const int nend = nbeg + (N_ / SPLIT);

    for (int n0 = nbeg; n0 < nend; n0 += NT) {
        __syncthreads();
        // stage fea tile: s_fea[i][c] = x[b,c,n0+i], STS.128 over 4 channels
        {
            int i = tid;
#pragma unroll
            for (int k = 0; k < C_ / 4; k++) {
                float4 v;
                v.x = xb[(size_t)(4 * k + 0) * N_ + n0 + i];
                v.y = xb[(size_t)(4 * k + 1) * N_ + n0 + i];
                v.z = xb[(size_t)(4 * k + 2) * N_ + n0 + i];
                v.w = xb[(size_t)(4 * k + 3) * N_ + n0 + i];
                *reinterpret_cast<float4*>(&s_fea[i][4 * k]) = v;
            }
            s_c[i] = __expf(g_c[b * N_ + n0 + i]);
        }
        __syncthreads();

        const float* adj_p = adj + (size_t)n0 * N_ + m0;
#pragma unroll 4
        for (int n = 0; n < NT; n++) {
            float en = s_c[n];
            float adj0 = __ldg(adj_p + (size_t)n * N_);
            float adj1 = __ldg(adj_p + (size_t)n * N_ + 128);
            float w0 = __fdividef(fminf(en, em0), en + em0) * (2.0f * adj0);
            float w1 = __fdividef(fminf(en, em1), en + em1) * (2.0f * adj1);
            unsigned long long w20, w21;
            asm("mov.b64 %0, {%1, %1};" : "=l"(w20) : "f"(w0));
            asm("mov.b64 %0, {%1, %1};" : "=l"(w21) : "f"(w1));
            unsigned row_addr =
                (unsigned)__cvta_generic_to_shared(&s_fea[n][0]);
#pragma unroll
            for (int p = 0; p < 8; p++) {
                unsigned long long d0, d1;
                asm("ld.shared.v2.u64 {%0, %1}, [%2];"
                    : "=l"(d0), "=l"(d1) : "r"(row_addr + 16 * p));
                asm("fma.rn.f32x2 %0, %1, %2, %0;"
                    : "+l"(accA[2 * p]) : "l"(d0), "l"(w20));
                asm("fma.rn.f32x2 %0, %1, %2, %0;"
                    : "+l"(accA[2 * p + 1]) : "l"(d1), "l"(w20));
                asm("fma.rn.f32x2 %0, %1, %2, %0;"
                    : "+l"(accB[2 * p]) : "l"(d0), "l"(w21));
                asm("fma.rn.f32x2 %0, %1, %2, %0;"
                    : "+l"(accB[2 * p + 1]) : "l"(d1), "l"(w21));
            }
        }
    }

    // write partials for both columns
    float* dst0 = &g_part[z][((size_t)b * C_) * N_ + m0];
#pragma unroll
    for (int p = 0; p < 16; p++) {
        float lo, hi;
        asm("mov.b64 {%0, %1}, %2;" : "=f"(lo), "=f"(hi) : "l"(accA[p]));
        dst0[(size_t)(2 * p) * N_] = lo;
        dst0[(size_t)(2 * p + 1) * N_] = hi;
    }
    float* dst1 = dst0 + 128;
#pragma unroll
    for (int p = 0; p < 16; p++) {
        float lo, hi;
        asm("mov.b64 {%0, %1}, %2;" : "=f"(lo), "=f"(hi) : "l"(accB[p]));
        dst1[(size_t)(2 * p) * N_] = lo;
        dst1[(size_t)(2 * p + 1) * N_] = hi;
    }
}

// out = relu(para * sum_z part[z]), vectorized float4
__global__ void combine_kernel(const float* __restrict__ para,
                               float* __restrict__ out) {
    int idx = blockIdx.x * blockDim.x + threadIdx.x;  // over B*C*N/4
    const float4* pp = reinterpret_cast<const float4*>(para);
    float4 s = reinterpret_cast<const float4*>(g_part[0])[idx];
#pragma unroll
    for (int z = 1; z < SPLIT; z++) {
        float4 v = reinterpret_cast<const float4*>(g_part[z])[idx];
        s.x += v.x; s.y += v.y; s.z += v.z; s.w += v.w;
    }
    float4 pv = pp[idx & (C_ * N_ / 4 - 1)];
    float4 o;
    o.x = fmaxf(s.x * pv.x, 0.f);
    o.y = fmaxf(s.y * pv.y, 0.f);
    o.z = fmaxf(s.z * pv.z, 0.f);
    o.w = fmaxf(s.w * pv.w, 0.f);
    reinterpret_cast<float4*>(out)[idx] = o;
}

extern "C" void kernel_launch(void* const* d_in, const int* in_sizes, int n_in,
                              void* d_out, int out_size) {
    const float* x    = (const float*)d_in[0];  // [8,32,64,64]
    const float* para = (const float*)d_in[1];  // [1,32,64,64]
    const float* adj  = (const float*)d_in[2];  // [4096,4096]
    float* out = (float*)d_out;                 // [8,32,64,64]

    mean_kernel<<<(B_ * N_ + 255) / 256, 256>>>(x);

    dim3 grid(N_ / 256, B_, SPLIT);
    gcn_partial_kernel<<<grid, 128>>>(x, adj);

    combine_kernel<<<(B_ * C_ * N_ / 4) / 256, 256>>>(para, out);
}

// round 5
// speedup vs baseline: 1.6643x; 1.1183x over previous
#include <cuda_runtime.h>

#define B_ 8
#define C_ 32
#define N_ 4096
#define NT 128
#define SPLIT 8

__device__ float g_c[B_ * N_];
__device__ float g_part[SPLIT][B_ * C_ * N_];

__global__ void mean_kernel(const float* __restrict__ x) {
    int idx = blockIdx.x * blockDim.x + threadIdx.x;
    if (idx >= B_ * N_) return;
    int b = idx >> 12;
    int n = idx & (N_ - 1);
    const float* p = x + ((size_t)b * C_) * N_ + n;
    float s = 0.f;
#pragma unroll
    for (int c = 0; c < C_; c++) s += p[(size_t)c * N_];
    g_c[idx] = s * (1.0f / C_);
}

// 2 output columns per thread (m0, m0+128), software-pipelined adj prefetch.
__global__ __launch_bounds__(128, 4)
void gcn_partial_kernel(const float* __restrict__ x,
                        const float* __restrict__ adj) {
    __shared__ float s_fea[NT][36];
    __shared__ float s_c[NT];

    const int tid = threadIdx.x;
    const int b = blockIdx.y;
    const int z = blockIdx.z;
    const int m0 = blockIdx.x * 256 + tid;

    const float em0 = __expf(g_c[b * N_ + m0]);
    const float em1 = __expf(g_c[b * N_ + m0 + 128]);

    unsigned long long accA[16], accB[16];
#pragma unroll
    for (int p = 0; p < 16; p++) { accA[p] = 0ull; accB[p] = 0ull; }

    const float* xb = x + (size_t)b * C_ * N_;
    const int nbeg = z * (N_ / SPLIT);
    const int nend = nbeg + (N_ / SPLIT);

    for (int n0 = nbeg; n0 < nend; n0 += NT) {
        __syncthreads();
        {
            int i = tid;
#pragma unroll
            for (int k = 0; k < C_ / 4; k++) {
                float4 v;
                v.x = xb[(size_t)(4 * k + 0) * N_ + n0 + i];
                v.y = xb[(size_t)(4 * k + 1) * N_ + n0 + i];
                v.z = xb[(size_t)(4 * k + 2) * N_ + n0 + i];
                v.w = xb[(size_t)(4 * k + 3) * N_ + n0 + i];
                *reinterpret_cast<float4*>(&s_fea[i][4 * k]) = v;
            }
            s_c[i] = __expf(g_c[b * N_ + n0 + i]);
        }
        __syncthreads();

        const float* ap = adj + (size_t)n0 * N_ + m0;

        // pipelined: buffers A/B each hold adj for a 4-n chunk (2 cols each)
        float bufA[8], bufB[8];
#pragma unroll
        for (int j = 0; j < 4; j++) {
            bufA[2 * j]     = __ldg(ap + (size_t)j * N_);
            bufA[2 * j + 1] = __ldg(ap + (size_t)j * N_ + 128);
        }

#define COMPUTE_CHUNK(BUF, CH)                                              \
        {                                                                   \
            _Pragma("unroll")                                               \
            for (int j = 0; j < 4; j++) {                                   \
                int n = (CH) * 4 + j;                                       \
                float en = s_c[n];                                          \
                float w0 = __fdividef(fminf(en, em0), en + em0) *           \
                           (2.0f * BUF[2 * j]);                             \
                float w1 = __fdividef(fminf(en, em1), en + em1) *           \
                           (2.0f * BUF[2 * j + 1]);                         \
                unsigned long long w20, w21;                                \
                asm("mov.b64 %0, {%1, %1};" : "=l"(w20) : "f"(w0));         \
                asm("mov.b64 %0, {%1, %1};" : "=l"(w21) : "f"(w1));         \
                unsigned ra =                                               \
                    (unsigned)__cvta_generic_to_shared(&s_fea[n][0]);       \
                _Pragma("unroll")                                           \
                for (int p = 0; p < 8; p++) {                               \
                    unsigned long long d0, d1;                              \
                    asm("ld.shared.v2.u64 {%0, %1}, [%2];"                  \
                        : "=l"(d0), "=l"(d1) : "r"(ra + 16 * p));           \
                    asm("fma.rn.f32x2 %0, %1, %2, %0;"                      \
                        : "+l"(accA[2 * p]) : "l"(d0), "l"(w20));           \
                    asm("fma.rn.f32x2 %0, %1, %2, %0;"                      \
                        : "+l"(accA[2 * p + 1]) : "l"(d1), "l"(w20));       \
                    asm("fma.rn.f32x2 %0, %1, %2, %0;"                      \
                        : "+l"(accB[2 * p]) : "l"(d0), "l"(w21));           \
                    asm("fma.rn.f32x2 %0, %1, %2, %0;"                      \
                        : "+l"(accB[2 * p + 1]) : "l"(d1), "l"(w21));       \
                }                                                           \
            }                                                               \
        }

#define PREFETCH_CHUNK(BUF, CH)                                             \
        {                                                                   \
            _Pragma("unroll")                                               \
            for (int j = 0; j < 4; j++) {                                   \
                BUF[2 * j]     = __ldg(ap + (size_t)((CH) * 4 + j) * N_);   \
                BUF[2 * j + 1] = __ldg(ap + (size_t)((CH) * 4 + j) * N_ + 128); \
            }                                                               \
        }

        for (int ch = 0; ch < NT / 4; ch += 2) {
            // prefetch chunk ch+1 into B, compute chunk ch from A
            PREFETCH_CHUNK(bufB, ch + 1);
            COMPUTE_CHUNK(bufA, ch);
            // prefetch chunk ch+2 into A (guarded), compute ch+1 from B
            if (ch + 2 < NT / 4) PREFETCH_CHUNK(bufA, ch + 2);
            COMPUTE_CHUNK(bufB, ch + 1);
        }
#undef COMPUTE_CHUNK
#undef PREFETCH_CHUNK
    }

    float* dst0 = &g_part[z][((size_t)b * C_) * N_ + m0];
#pragma unroll
    for (int p = 0; p < 16; p++) {
        float lo, hi;
        asm("mov.b64 {%0, %1}, %2;" : "=f"(lo), "=f"(hi) : "l"(accA[p]));
        dst0[(size_t)(2 * p) * N_] = lo;
        dst0[(size_t)(2 * p + 1) * N_] = hi;
    }
    float* dst1 = dst0 + 128;
#pragma unroll
    for (int p = 0; p < 16; p++) {
        float lo, hi;
        asm("mov.b64 {%0, %1}, %2;" : "=f"(lo), "=f"(hi) : "l"(accB[p]));
        dst1[(size_t)(2 * p) * N_] = lo;
        dst1[(size_t)(2 * p + 1) * N_] = hi;
    }
}

__global__ void combine_kernel(const float* __restrict__ para,
                               float* __restrict__ out) {
    int idx = blockIdx.x * blockDim.x + threadIdx.x;
    const float4* pp = reinterpret_cast<const float4*>(para);
    float4 s = reinterpret_cast<const float4*>(g_part[0])[idx];
#pragma unroll
    for (int z = 1; z < SPLIT; z++) {
        float4 v = reinterpret_cast<const float4*>(g_part[z])[idx];
        s.x += v.x; s.y += v.y; s.z += v.z; s.w += v.w;
    }
    float4 pv = pp[idx & (C_ * N_ / 4 - 1)];
    float4 o;
    o.x = fmaxf(s.x * pv.x, 0.f);
    o.y = fmaxf(s.y * pv.y, 0.f);
    o.z = fmaxf(s.z * pv.z, 0.f);
    o.w = fmaxf(s.w * pv.w, 0.f);
    reinterpret_cast<float4*>(out)[idx] = o;
}

extern "C" void kernel_launch(void* const* d_in, const int* in_sizes, int n_in,
                              void* d_out, int out_size) {
    const float* x    = (const float*)d_in[0];
    const float* para = (const float*)d_in[1];
    const float* adj  = (const float*)d_in[2];
    float* out = (float*)d_out;

    mean_kernel<<<(B_ * N_ + 255) / 256, 256>>>(x);

    dim3 grid(N_ / 256, B_, SPLIT);
    gcn_partial_kernel<<<grid, 128>>>(x, adj);

    combine_kernel<<<(B_ * C_ * N_ / 4) / 256, 256>>>(para, out);
}

// round 7
// speedup vs baseline: 2.5183x; 1.5131x over previous
#include <cuda_runtime.h>
#include <cstdint>

#define B_ 8
#define C_ 32
#define N_ 4096
#define KC 32
#define SPLIT 2

__device__ float g_e[B_ * N_];
__device__ float g_part[SPLIT][B_ * C_ * N_];

__global__ void mean_exp_kernel(const float* __restrict__ x) {
    int idx = blockIdx.x * blockDim.x + threadIdx.x;
    if (idx >= B_ * N_) return;
    int b = idx >> 12, n = idx & (N_ - 1);
    const float* p = x + ((size_t)b * C_) * N_ + n;
    float s = 0.f;
#pragma unroll
    for (int c = 0; c < C_; c++) s += p[(size_t)c * N_];
    g_e[idx] = __expf(s * (1.0f / C_));
}

__device__ __forceinline__ uint32_t to_tf32(float f) {
    uint32_t u;
    asm("cvt.rna.tf32.f32 %0, %1;" : "=r"(u) : "f"(f));
    return u;
}

#define MMA_TF32(acc, a, b0v, b1v)                                          \
    asm volatile(                                                           \
        "mma.sync.aligned.m16n8k8.row.col.f32.tf32.tf32.f32 "               \
        "{%0,%1,%2,%3}, {%4,%5,%6,%7}, {%8,%9}, {%0,%1,%2,%3};"             \
        : "+f"((acc)[0]), "+f"((acc)[1]), "+f"((acc)[2]), "+f"((acc)[3])    \
        : "r"((a)[0]), "r"((a)[1]), "r"((a)[2]), "r"((a)[3]),               \
          "r"(b0v), "r"(b1v))

// CTA: 256 thr (8 warps), m-block 128 (warp -> m16), batch pair, K-split.
// W[m,n] = 2*min(e_n,e_m)/(e_n+e_m) * adj[n,m]; out^T = W @ fea^T per batch.
__global__ __launch_bounds__(256, 2)
void gcn_mma_kernel(const float* __restrict__ x,
                    const float* __restrict__ adj) {
    __shared__ uint32_t s_B[2][32 * 32];   // [batch][c*32 + swz(n)], tf32
    __shared__ float s_e[2][KC];

    const int tid = threadIdx.x;
    const int warp = tid >> 5;
    const int lane = tid & 31;
    const int q = lane >> 2;               // 0..7
    const int r = lane & 3;                // 0..3
    const int mb = blockIdx.x * 128 + warp * 16;
    const int bp = blockIdx.y;
    const int b0 = 2 * bp, b1 = 2 * bp + 1;
    const int z = blockIdx.z;
    const int nbeg = z * (N_ / SPLIT);
    const int nend = nbeg + (N_ / SPLIT);

    // e_m for this thread's two rows, both batches (fixed all kernel)
    const float em0a = g_e[b0 * N_ + mb + q];
    const float em0b = g_e[b0 * N_ + mb + q + 8];
    const float em1a = g_e[b1 * N_ + mb + q];
    const float em1b = g_e[b1 * N_ + mb + q + 8];

    float acc[2][4][4];
#pragma unroll
    for (int bi = 0; bi < 2; bi++)
#pragma unroll
        for (int cf = 0; cf < 4; cf++)
#pragma unroll
            for (int i = 0; i < 4; i++) acc[bi][cf][i] = 0.f;

    // staging map: 2048 elems / 256 thr = 8 each
    const int st_b = tid >> 7;             // 0/1
    const int st_c = (tid >> 2) & 31;      // channel
    const int st_ng = (tid & 3) * 8;       // 8 consecutive n
    const float* st_x = x + (((size_t)(2 * bp + st_b) * C_ + st_c) << 12);
    const int st_sw = 4 * (st_c & 7);

    for (int n0 = nbeg; n0 < nend; n0 += KC) {
        __syncthreads();
        {
            float4 u0 = *reinterpret_cast<const float4*>(st_x + n0 + st_ng);
            float4 u1 = *reinterpret_cast<const float4*>(st_x + n0 + st_ng + 4);
            const float* uv = &u0.x;
            uint32_t* dst = &s_B[st_b][st_c * 32];
#pragma unroll
            for (int i = 0; i < 8; i++) {
                float v = (i < 4) ? uv[i] : (&u1.x)[i - 4];
                dst[(st_ng + i + st_sw) & 31] = to_tf32(v);
            }
            if (tid < 64)
                s_e[tid >> 5][tid & 31] =
                    g_e[(2 * bp + (tid >> 5)) * N_ + n0 + (tid & 31)];
        }
        __syncthreads();

#pragma unroll
        for (int ks = 0; ks < KC / 8; ks++) {
            const int k0 = ks * 8;

            // adj for the 4 A-slots (shared by both batches)
            const float* ap = adj + (size_t)(n0 + k0 + r) * N_ + mb + q;
            float adj2[4];
            adj2[0] = 2.0f * __ldg(ap);
            adj2[1] = 2.0f * __ldg(ap + 8);
            adj2[2] = 2.0f * __ldg(ap + (size_t)4 * N_);
            adj2[3] = 2.0f * __ldg(ap + (size_t)4 * N_ + 8);

            const float en0_0 = s_e[0][k0 + r];
            const float en0_4 = s_e[0][k0 + r + 4];
            const float en1_0 = s_e[1][k0 + r];
            const float en1_4 = s_e[1][k0 + r + 4];

            uint32_t a0f[4], a1f[4];
            // slots: 0:(m+0,k+0) 1:(m+8,k+0) 2:(m+0,k+4) 3:(m+8,k+4)
#pragma unroll
            for (int s = 0; s < 4; s++) {
                const float en0 = (s < 2) ? en0_0 : en0_4;
                const float en1 = (s < 2) ? en1_0 : en1_4;
                const float e0 = (s & 1) ? em0b : em0a;
                const float e1 = (s & 1) ? em1b : em1a;
                float d0 = en0 + e0, d1 = en1 + e1;
                float rr;
                asm("rcp.approx.f32 %0, %1;" : "=f"(rr) : "f"(d0 * d1));
                float t = adj2[s] * rr;
                a0f[s] = to_tf32(fminf(en0, e0) * d1 * t);
                a1f[s] = to_tf32(fminf(en1, e1) * d0 * t);
            }

            const int off0 = (k0 + r + 4 * q) & 31;
            const int off4 = (k0 + r + 4 + 4 * q) & 31;
#pragma unroll
            for (int cf = 0; cf < 4; cf++) {
                const int row = (cf * 8 + q) * 32;
                uint32_t b00 = s_B[0][row + off0];
                uint32_t b01 = s_B[0][row + off4];
                uint32_t b10 = s_B[1][row + off0];
                uint32_t b11 = s_B[1][row + off4];
                MMA_TF32(acc[0][cf], a0f, b00, b01);
                MMA_TF32(acc[1][cf], a1f, b10, b11);
            }
        }
    }

    // write partials: D frag (row q(+8), col 2r(+1)) per cf per batch
#pragma unroll
    for (int bi = 0; bi < 2; bi++) {
        float* dst = g_part[z] + (((size_t)(2 * bp + bi) * C_) << 12);
#pragma unroll
        for (int cf = 0; cf < 4; cf++) {
            int c0 = cf * 8 + 2 * r;
            int m0 = mb + q;
            dst[((size_t)c0 << 12) + m0] = acc[bi][cf][0];
            dst[((size_t)(c0 + 1) << 12) + m0] = acc[bi][cf][1];
            dst[((size_t)c0 << 12) + m0 + 8] = acc[bi][cf][2];
            dst[((size_t)(c0 + 1) << 12) + m0 + 8] = acc[bi][cf][3];
        }
    }
}

__global__ void combine_kernel(const float* __restrict__ para,
                               float* __restrict__ out) {
    int idx = blockIdx.x * blockDim.x + threadIdx.x;
    const float4* pp = reinterpret_cast<const float4*>(para);
    float4 s = reinterpret_cast<const float4*>(g_part[0])[idx];
    float4 v = reinterpret_cast<const float4*>(g_part[1])[idx];
    s.x += v.x; s.y += v.y; s.z += v.z; s.w += v.w;
    float4 pv = pp[idx & (C_ * N_ / 4 - 1)];
    float4 o;
    o.x = fmaxf(s.x * pv.x, 0.f);
    o.y = fmaxf(s.y * pv.y, 0.f);
    o.z = fmaxf(s.z * pv.z, 0.f);
    o.w = fmaxf(s.w * pv.w, 0.f);
    reinterpret_cast<float4*>(out)[idx] = o;
}

extern "C" void kernel_launch(void* const* d_in, const int* in_sizes, int n_in,
                              void* d_out, int out_size) {
    const float* x    = (const float*)d_in[0];  // [8,32,64,64]
    const float* para = (const float*)d_in[1];  // [1,32,64,64]
    const float* adj  = (const float*)d_in[2];  // [4096,4096]
    float* out = (float*)d_out;

    mean_exp_kernel<<<(B_ * N_ + 255) / 256, 256>>>(x);

    dim3 grid(N_ / 128, B_ / 2, SPLIT);
    gcn_mma_kernel<<<grid, 256>>>(x, adj);

    combine_kernel<<<(B_ * C_ * N_ / 4) / 256, 256>>>(para, out);
}